// round 16
// baseline (speedup 1.0000x reference)
#include <cuda_runtime.h>
#include <cuda_fp16.h>
#include <cstdint>

// ============================================================================
// Problem dims (fixed by setup_inputs)
// ============================================================================
#define DIN    2048
#define DOUT   2048
#define MROWS  8192        // B*S = 4*2048
#define GROUPS 64          // DIN/32

// ============================================================================
// Scratch (device globals; no allocation allowed)
// ============================================================================
__device__ __half g_xq[(size_t)MROWS * DIN];   // quantized x as exact integers in fp16
__device__ __half g_wh[(size_t)DOUT * DIN];    // dequantized weights in fp16
__device__ float  g_xscale[MROWS];             // per-token scale

// ============================================================================
// Portable PTX helpers (sm_80-level only: cp.async, ldmatrix, mma.sync)
// ============================================================================
__device__ __forceinline__ uint32_t smem_to_u32(const void* smem_ptr) {
    uint32_t addr;
    asm("{ .reg .u64 tmp; cvta.to.shared.u64 tmp, %1; cvt.u32.u64 %0, tmp; }"
        : "=r"(addr) : "l"(smem_ptr));
    return addr;
}

__device__ __forceinline__ void cp_async16(uint32_t smem_addr, const void* gptr) {
    asm volatile("cp.async.cg.shared.global [%0], [%1], 16;"
                 :: "r"(smem_addr), "l"(gptr));
}

template <int N>
__device__ __forceinline__ void cp_wait() {
    asm volatile("cp.async.wait_group %0;" :: "n"(N) : "memory");
}

__device__ __forceinline__ void ldsm_x4(uint32_t* r, uint32_t addr) {
    asm volatile("ldmatrix.sync.aligned.m8n8.x4.shared.b16 {%0,%1,%2,%3}, [%4];"
                 : "=r"(r[0]), "=r"(r[1]), "=r"(r[2]), "=r"(r[3])
                 : "r"(addr));
}

__device__ __forceinline__ void mma16816(float* d, const uint32_t* a,
                                         uint32_t b0, uint32_t b1) {
    asm volatile(
        "mma.sync.aligned.m16n8k16.row.col.f32.f16.f16.f32 "
        "{%0,%1,%2,%3}, {%4,%5,%6,%7}, {%8,%9}, {%0,%1,%2,%3};"
        : "+f"(d[0]), "+f"(d[1]), "+f"(d[2]), "+f"(d[3])
        : "r"(a[0]), "r"(a[1]), "r"(a[2]), "r"(a[3]), "r"(b0), "r"(b1));
}

// ============================================================================
// Kernel 1 (merged prep):
//   blocks [0, MROWS/8): quantize x — ONE WARP PER ROW, row held in
//     registers (16 float4/lane), butterfly min/max (no smem, no barriers),
//     all lanes redundantly compute scale/zp (exact), 8x STG.128 out.
//   blocks [MROWS/8, MROWS/8 + 2048): dequantize W (8 elements per thread).
// Quant math identical to prior rounds: q - zp == clip(rint(x*rs), lo, hi).
// ============================================================================
static constexpr int QBLOCKS = MROWS / 8;            // 1024 (8 warps/block)

__global__ void __launch_bounds__(256)
prep_kernel(const float* __restrict__ x,
            const int* __restrict__ wi,
            const float* __restrict__ ws,
            const float* __restrict__ wz) {
    const int tid = threadIdx.x;

    if (blockIdx.x < QBLOCKS) {
        // ---- per-token asymmetric int8 fake-quant of x (warp per row) ----
        const int row  = blockIdx.x * 8 + (tid >> 5);
        const int lane = tid & 31;
        const float4* xr = (const float4*)(x + (size_t)row * DIN);

        // lane owns elements [8*lane + 256*j, +8) for j = 0..7
        float4 va[8], vb[8];
        #pragma unroll
        for (int j = 0; j < 8; j++) {
            va[j] = xr[2 * lane + 64 * j];
            vb[j] = xr[2 * lane + 64 * j + 1];
        }

        float mn = 0.0f, mx = 0.0f;   // reference min/max include 0
        #pragma unroll
        for (int j = 0; j < 8; j++) {
            mn = fminf(mn, fminf(fminf(va[j].x, va[j].y), fminf(va[j].z, va[j].w)));
            mn = fminf(mn, fminf(fminf(vb[j].x, vb[j].y), fminf(vb[j].z, vb[j].w)));
            mx = fmaxf(mx, fmaxf(fmaxf(va[j].x, va[j].y), fmaxf(va[j].z, va[j].w)));
            mx = fmaxf(mx, fmaxf(fmaxf(vb[j].x, vb[j].y), fmaxf(vb[j].z, vb[j].w)));
        }
        #pragma unroll
        for (int off = 16; off > 0; off >>= 1) {
            mn = fminf(mn, __shfl_xor_sync(0xffffffffu, mn, off));
            mx = fmaxf(mx, __shfl_xor_sync(0xffffffffu, mx, off));
        }

        // All lanes compute identical scale/zp (deterministic fp ops).
        float scale = fmaxf(__fdiv_rn(mx - mn, 255.0f), 1.1920929e-07f);
        float zpf = -128.0f - rintf(__fdiv_rn(mn, scale));
        zpf = fminf(fmaxf(zpf, -128.0f), 127.0f);
        if (lane == 0) g_xscale[row] = scale;

        const float rs = __frcp_rn(scale);
        const float lo = -128.0f - zpf;       // lo clip bound (q - zp space)
        const float hi = lo + 255.0f;         // 127 - zp, exact

        // q - zp = clip(rint(x*rs), lo, hi) : integer in [-255,255]
        auto qd = [&](float xv) -> float {
            return fminf(fmaxf(rintf(xv * rs), lo), hi);
        };

        uint4* dst = (uint4*)(g_xq + (size_t)row * DIN);
        #pragma unroll
        for (int j = 0; j < 8; j++) {
            uint4 pk;
            __half2 h;
            h = __floats2half2_rn(qd(va[j].x), qd(va[j].y)); pk.x = *(uint32_t*)&h;
            h = __floats2half2_rn(qd(va[j].z), qd(va[j].w)); pk.y = *(uint32_t*)&h;
            h = __floats2half2_rn(qd(vb[j].x), qd(vb[j].y)); pk.z = *(uint32_t*)&h;
            h = __floats2half2_rn(qd(vb[j].z), qd(vb[j].w)); pk.w = *(uint32_t*)&h;
            dst[lane + 32 * j] = pk;
        }
    } else {
        // ---- grouped-int4 dequant of W into fp16 (8 elements/thread) ----
        const int t = (blockIdx.x - QBLOCKS) * 256 + tid;   // 8-element chunk id
        const int4* wrow = (const int4*)wi;
        const int4 wa = wrow[2 * t];
        const int4 wb = wrow[2 * t + 1];
        const int base = t << 3;
        const int o = base >> 11;                 // / DIN
        const int g = (base & (DIN - 1)) >> 5;    // group of 32 (8 aligned inside)
        const float s = ws[o * GROUPS + g];
        const float z = wz[o * GROUPS + g];
        uint4 pk;
        __half2 h;
        h = __floats2half2_rn(((float)wa.x - z) * s, ((float)wa.y - z) * s); pk.x = *(uint32_t*)&h;
        h = __floats2half2_rn(((float)wa.z - z) * s, ((float)wa.w - z) * s); pk.y = *(uint32_t*)&h;
        h = __floats2half2_rn(((float)wb.x - z) * s, ((float)wb.y - z) * s); pk.z = *(uint32_t*)&h;
        h = __floats2half2_rn(((float)wb.z - z) * s, ((float)wb.w - z) * s); pk.w = *(uint32_t*)&h;
        ((uint4*)g_wh)[t] = pk;
    }
}

// ============================================================================
// Kernel 2: fp16 mma.sync GEMM (NT), CTA 128x128, warp tile 32x64, BK=64,
// 3-stage cp.async pipeline (prefetch distance 2), one barrier per iter,
// 2 CTAs/SM, register-double-buffered fragments. (Frozen best config, 215us —
// at the sm_103 legacy HMMA issue-rate ceiling, rt ~= 15.2 cyc/SMSP.)
//   out[m, n] = g_xscale[m] * sum_k g_xq[m,k] * g_wh[n,k]
//
// SMEM rows: 64 fp16 data + 8 fp16 pad = 144B stride (conflict-free ldmatrix;
// 16B-aligned cp.async chunks, 8 lanes per row -> fully coalesced GMEM).
// ============================================================================
static constexpr int BM = 128;
static constexpr int BN = 128;
static constexpr int BK = 64;
static constexpr int KITERS = DIN / BK;            // 32
static constexpr int SROWB = 144;                  // bytes per smem row
static constexpr int TILE_B = 128 * SROWB;         // 18432 per operand
static constexpr int STAGE_B = 2 * TILE_B;         // 36864 (A + B)
static constexpr int NSTAGES = 3;
static constexpr int GEMM_SMEM = NSTAGES * STAGE_B;  // 110592; x2 CTAs = 221KB

__global__ void __launch_bounds__(256, 2)
qgemm_kernel(float* __restrict__ out) {
    extern __shared__ char sm[];
    const uint32_t sbase = smem_to_u32(sm);
    const int tid  = threadIdx.x;
    const int lane = tid & 31;
    const int wid  = tid >> 5;
    const int warp_m = wid & 3;    // 4 m-tiles of 32 rows
    const int warp_n = wid >> 2;   // 2 n-tiles of 64 cols
    const int n0 = blockIdx.x * BN;
    const int m0 = blockIdx.y * BM;

    const __half* ga = g_xq + (size_t)m0 * DIN;
    const __half* gb = g_wh + (size_t)n0 * DIN;

    auto load_stage = [&](int s, int k0) {
        const uint32_t abase = sbase + (uint32_t)s * STAGE_B;
        const uint32_t bbase = abase + (uint32_t)TILE_B;
        #pragma unroll
        for (int it = 0; it < 4; it++) {
            int c = tid + it * 256;          // 0..1023, one 16B chunk each
            int r = c >> 3;                  // row 0..127
            int colh = (c & 7) * 8;          // column in halves
            uint32_t soff = (uint32_t)(r * SROWB + colh * 2);
            cp_async16(abase + soff, ga + (size_t)r * DIN + k0 + colh);
            cp_async16(bbase + soff, gb + (size_t)r * DIN + k0 + colh);
        }
        asm volatile("cp.async.commit_group;" ::: "memory");
    };

    float acc[2][8][4];
    #pragma unroll
    for (int mi = 0; mi < 2; mi++)
        #pragma unroll
        for (int p = 0; p < 8; p++)
            #pragma unroll
            for (int j = 0; j < 4; j++)
                acc[mi][p][j] = 0.0f;

    load_stage(0, 0);
    load_stage(1, BK);

    // ldmatrix lane addressing: lanes 0-15 -> rows, lanes 16-31 -> +16B in k
    const uint32_t lrow = (uint32_t)(lane & 15);
    const uint32_t lkof = (uint32_t)((lane >> 4) * 16);   // bytes

    int sc = 0;
    for (int i = 0; i < KITERS; i++) {
        if (i + 2 < KITERS) cp_wait<1>(); else cp_wait<0>();
        __syncthreads();
        if (i + 2 < KITERS) {
            int sl = sc + 2; if (sl >= NSTAGES) sl -= NSTAGES;
            load_stage(sl, (i + 2) * BK);
        }

        const uint32_t abase = sbase + (uint32_t)sc * STAGE_B;
        const uint32_t bbase = abase + (uint32_t)TILE_B;
        const uint32_t arow0 = abase + (uint32_t)(warp_m * 32 + lrow) * SROWB + lkof;
        const uint32_t brow0 = bbase + (uint32_t)(warp_n * 64 + lrow) * SROWB + lkof;

        // Double-buffered fragments: load ka+1 while MMAs of ka execute.
        uint32_t a[2][2][4];
        uint32_t bq[2][4][4];

        // prime ka = 0
        ldsm_x4(a[0][0], arow0);
        ldsm_x4(a[0][1], arow0 + 16u * SROWB);
        #pragma unroll
        for (int t = 0; t < 4; t++)
            ldsm_x4(bq[0][t], brow0 + (uint32_t)(t * 16) * SROWB);

        #pragma unroll
        for (int ka = 0; ka < 4; ka++) {
            const int cur = ka & 1;
            const int nxt = cur ^ 1;
            if (ka < 3) {
                const uint32_t kb2 = (uint32_t)((ka + 1) * 32);
                ldsm_x4(a[nxt][0], arow0 + kb2);
                ldsm_x4(a[nxt][1], arow0 + 16u * SROWB + kb2);
                #pragma unroll
                for (int t = 0; t < 4; t++)
                    ldsm_x4(bq[nxt][t], brow0 + (uint32_t)(t * 16) * SROWB + kb2);
            }
            #pragma unroll
            for (int mi = 0; mi < 2; mi++) {
                #pragma unroll
                for (int t = 0; t < 4; t++) {
                    // x4 B load t covers n-atoms 2t (regs 0,2) and 2t+1 (1,3)
                    mma16816(acc[mi][2 * t],     a[cur][mi], bq[cur][t][0], bq[cur][t][2]);
                    mma16816(acc[mi][2 * t + 1], a[cur][mi], bq[cur][t][1], bq[cur][t][3]);
                }
            }
        }
        sc++; if (sc == NSTAGES) sc = 0;
    }

    // Epilogue: scale by per-token scale, store fp32.
    const int qrow = lane >> 2;          // 0..7
    const int qcol = (lane & 3) * 2;     // 0,2,4,6
    #pragma unroll
    for (int mi = 0; mi < 2; mi++) {
        const int mrow0 = m0 + warp_m * 32 + mi * 16 + qrow;
        const float sc0 = g_xscale[mrow0];
        const float sc1 = g_xscale[mrow0 + 8];
        float* o0 = out + (size_t)mrow0 * DOUT + n0 + warp_n * 64 + qcol;
        float* o1 = o0 + (size_t)8 * DOUT;
        #pragma unroll
        for (int p = 0; p < 8; p++) {
            *(float2*)(o0 + p * 8) = make_float2(sc0 * acc[mi][p][0],
                                                 sc0 * acc[mi][p][1]);
            *(float2*)(o1 + p * 8) = make_float2(sc1 * acc[mi][p][2],
                                                 sc1 * acc[mi][p][3]);
        }
    }
}

// ============================================================================
// Launch
// ============================================================================
extern "C" void kernel_launch(void* const* d_in, const int* in_sizes, int n_in,
                              void* d_out, int out_size) {
    (void)in_sizes; (void)n_in; (void)out_size;
    const float* x  = (const float*)d_in[0];
    const int*   wi = (const int*)d_in[1];
    const float* ws = (const float*)d_in[2];
    const float* wz = (const float*)d_in[3];
    float* out = (float*)d_out;

    cudaFuncSetAttribute(qgemm_kernel,
                         cudaFuncAttributeMaxDynamicSharedMemorySize, GEMM_SMEM);

    prep_kernel<<<QBLOCKS + (DOUT * DIN) / 2048, 256>>>(x, wi, ws, wz);
    qgemm_kernel<<<dim3(DOUT / BN, MROWS / BM), 256, GEMM_SMEM>>>(out);
}